// round 9
// baseline (speedup 1.0000x reference)
#include <cuda_runtime.h>
#include <cuda_fp16.h>

typedef unsigned int u32;
typedef unsigned short u16;

#define SEQL 1000
#define CL   4
#define NT   256
#define GRID 128
#define NBC  16

// smem layout
#define HROW 528
#define HR4  132
#define HBUF (16 * HROW)                      // one hcat buffer (16 batches x 256k fp16 + pad)
#define GROW 260                              // gst row stride (f32 words)
#define OFF_HCAT 0u
#define OFF_GST  (2u * HBUF)                  // [16 batch][260] f32 ; rows 0-127 L2 gates, 128-255 L1 gates
#define OFF_X    (OFF_GST + 16u * GROW * 4u)  // [16][1000] f32
#define OFF_WLIN (OFF_X + 16u * SEQL * 4u)    // [128] f32
#define OFF_MB   (OFF_WLIN + 512u)            // mbarrier (8 B)
#define SMEM_TOTAL (OFF_MB + 32u)

static __device__ __forceinline__ u32 s2u(const void* p) {
    u32 a; asm("{ .reg .u64 t; cvta.to.shared.u64 t, %1; cvt.u32.u64 %0, t; }" : "=r"(a) : "l"(p));
    return a;
}
static __device__ __forceinline__ u32 mapa_rk(u32 addr, u32 rk) {
    u32 r; asm("mapa.shared::cluster.u32 %0, %1, %2;" : "=r"(r) : "r"(addr), "r"(rk));
    return r;
}
static __device__ __forceinline__ void stc_u32(u32 a, u32 v) {
    asm volatile("st.shared::cluster.u32 [%0], %1;" :: "r"(a), "r"(v) : "memory");
}
#define CSYNC() do { asm volatile("barrier.cluster.arrive.aligned;" ::: "memory"); \
                     asm volatile("barrier.cluster.wait.aligned;" ::: "memory"); } while (0)

static __device__ __forceinline__ void mbar_arrive_remote(u32 raddr) {
    asm volatile("mbarrier.arrive.release.cluster.shared::cluster.b64 _, [%0];"
                 :: "r"(raddr) : "memory");
}
static __device__ __forceinline__ void mbar_wait(u32 addr, u32 parity) {
    asm volatile(
        "{\n\t.reg .pred P;\n"
        "W%=:\n\tmbarrier.try_wait.parity.acquire.cluster.shared::cta.b64 P, [%0], %1;\n"
        "\t@!P bra W%=;\n\t}"
        :: "r"(addr), "r"(parity) : "memory");
}

static __device__ __forceinline__ void mma16816(float* d, const u32* a, u32 b0, u32 b1) {
    asm volatile("mma.sync.aligned.m16n8k16.row.col.f32.f16.f16.f32 "
        "{%0,%1,%2,%3}, {%4,%5,%6,%7}, {%8,%9}, {%0,%1,%2,%3};"
        : "+f"(d[0]), "+f"(d[1]), "+f"(d[2]), "+f"(d[3])
        : "r"(a[0]), "r"(a[1]), "r"(a[2]), "r"(a[3]), "r"(b0), "r"(b1));
}
static __device__ __forceinline__ void ldmx4(u32& r0, u32& r1, u32& r2, u32& r3, u32 addr) {
    asm volatile("ldmatrix.sync.aligned.m8n8.x4.shared.b16 {%0,%1,%2,%3}, [%4];"
        : "=r"(r0), "=r"(r1), "=r"(r2), "=r"(r3) : "r"(addr));
}
static __device__ __forceinline__ float tanha(float x) {
    float y; asm("tanh.approx.f32 %0, %1;" : "=f"(y) : "f"(x)); return y;
}
static __device__ __forceinline__ float siga(float x) {
    return fmaf(tanha(0.5f * x), 0.5f, 0.5f);
}
static __device__ __forceinline__ u32 f2h2(float lo, float hi) {
    __half2 h = __floats2half2_rn(lo, hi);
    return *reinterpret_cast<u32*>(&h);
}

__global__ __launch_bounds__(NT, 1) __cluster_dims__(CL, 1, 1)
void lstm_fused_kernel(const float* __restrict__ x,
                       const float* __restrict__ w_ih1,
                       const float* __restrict__ w_hh1,
                       const float* __restrict__ b_ih1,
                       const float* __restrict__ b_hh1,
                       const float* __restrict__ w_ih2,
                       const float* __restrict__ w_hh2,
                       const float* __restrict__ b_ih2,
                       const float* __restrict__ b_hh2,
                       const float* __restrict__ w_lin,
                       const float* __restrict__ b_lin,
                       float* __restrict__ out)
{
    extern __shared__ __align__(16) char smem[];
    const u32 sb = s2u(smem);
    const int tid  = threadIdx.x;
    const int lane = tid & 31;
    const int w    = tid >> 5;
    u32 rank; asm("mov.u32 %0, %%cluster_ctarank;" : "=r"(rank));
    const int b0 = (blockIdx.x >> 2) * NBC;

    const int fg = lane >> 2;
    const int ft = lane & 3;

    // ---------- A fragments (fp16 weights, registers, loaded once)
    const int r0 = w * 16 + fg;
    const int r1 = r0 + 8;
    const int G0 = (r0 >> 5) * 128 + (int)rank * 32 + (r0 & 31);
    const int G1 = (r1 >> 5) * 128 + (int)rank * 32 + (r1 & 31);

    u32 A1[8][4], A2[16][4];
    #pragma unroll
    for (int kt = 0; kt < 8; kt++) {
        int k = kt * 16 + 2 * ft;
        A1[kt][0] = f2h2(w_hh1[G0 * 128 + k],     w_hh1[G0 * 128 + k + 1]);
        A1[kt][1] = f2h2(w_hh1[G1 * 128 + k],     w_hh1[G1 * 128 + k + 1]);
        A1[kt][2] = f2h2(w_hh1[G0 * 128 + k + 8], w_hh1[G0 * 128 + k + 9]);
        A1[kt][3] = f2h2(w_hh1[G1 * 128 + k + 8], w_hh1[G1 * 128 + k + 9]);
    }
    #pragma unroll
    for (int kt = 0; kt < 16; kt++) {
        int k = kt * 16 + 2 * ft;
        const float* Wa = (k < 128)     ? (w_ih2 + k)     : (w_hh2 + k - 128);
        const float* Wb = (k + 8 < 128) ? (w_ih2 + k + 8) : (w_hh2 + k + 8 - 128);
        A2[kt][0] = f2h2(Wa[G0 * 128],     Wa[G0 * 128 + 1]);
        A2[kt][1] = f2h2(Wa[G1 * 128],     Wa[G1 * 128 + 1]);
        A2[kt][2] = f2h2(Wb[G0 * 128],     Wb[G0 * 128 + 1]);
        A2[kt][3] = f2h2(Wb[G1 * 128],     Wb[G1 * 128 + 1]);
    }

    // ---------- init smem
    for (u32 i = (u32)tid; i < 2u * HBUF / 4u; i += NT)
        ((u32*)smem)[i] = 0u;
    float* xsh = (float*)(smem + OFF_X);
    for (int i = tid; i < NBC * SEQL; i += NT)
        xsh[i] = x[b0 * SEQL + i];
    float* wlin_s = (float*)(smem + OFF_WLIN);
    if (tid < 128) wlin_s[tid] = w_lin[tid];
    if (tid == 0)
        asm volatile("mbarrier.init.shared.b64 [%0], %1;" :: "r"(sb + OFF_MB), "r"((u32)CL) : "memory");

    // ---------- elementwise mapping: L (0=layer1, 1=layer2), unit pair up, batches bq, bq+8
    const int L  = tid >> 7;
    const int up = (tid >> 3) & 15;
    const int bq = tid & 7;
    float wiA[4], wiB[4], bsA[4], bsB[4];
    #pragma unroll
    for (int g = 0; g < 4; g++) {
        int GA = g * 128 + (int)rank * 32 + 2 * up;
        int GB = GA + 1;
        if (L == 0) {
            wiA[g] = w_ih1[GA];            wiB[g] = w_ih1[GB];
            bsA[g] = b_ih1[GA] + b_hh1[GA]; bsB[g] = b_ih1[GB] + b_hh1[GB];
        } else {
            wiA[g] = 0.f;                   wiB[g] = 0.f;
            bsA[g] = b_ih2[GA] + b_hh2[GA]; bsB[g] = b_ih2[GB] + b_hh2[GB];
        }
    }
    float cA[2] = {0.f, 0.f}, cB[2] = {0.f, 0.f};
    const float blin = b_lin[0];

    u32 rb[CL], rmb[CL];
    #pragma unroll
    for (u32 rk = 0; rk < CL; rk++) {
        rb[rk]  = mapa_rk(sb + OFF_HCAT, rk);
        rmb[rk] = mapa_rk(sb + OFF_MB, rk);
    }
    const u32 kbyte = (u32)((L ? 128 : 0) + (int)rank * 32 + 2 * up) * 2u;

    float* gst = (float*)(smem + OFF_GST);
    const int grow_base = L ? 0 : 128;    // gst row offset for this thread's layer

    // ldmatrix per-lane base offset (proven in R7):
    const u32 ld_off = (u32)(((lane & 7) + ((lane >> 4) << 3)) * HROW + (((lane >> 3) & 1) << 4));

    __syncthreads();
    CSYNC();   // all CTAs zeroed buffers + mbarrier initialized

    // ---------- prologue: h1(0) from x(0) only (h1(-1)=0); write into buffer 0
    if (L == 0) {
        #pragma unroll
        for (int j = 0; j < 2; j++) {
            int b = bq + 8 * j;
            float xv = xsh[b * SEQL];
            float iA = siga(fmaf(wiA[0], xv, bsA[0]));
            float fA = siga(fmaf(wiA[1], xv, bsA[1]));
            float gA = tanha(fmaf(wiA[2], xv, bsA[2]));
            float oA = siga(fmaf(wiA[3], xv, bsA[3]));
            cA[j] = iA * gA;
            float hA = oA * tanha(cA[j]);
            float iB = siga(fmaf(wiB[0], xv, bsB[0]));
            float fB = siga(fmaf(wiB[1], xv, bsB[1]));
            float gB = tanha(fmaf(wiB[2], xv, bsB[2]));
            float oB = siga(fmaf(wiB[3], xv, bsB[3]));
            cB[j] = iB * gB;
            float hB = oB * tanha(cB[j]);
            u32 pk = f2h2(hA, hB);
            u32 off = (u32)b * HROW + kbyte;          // buffer 0
            stc_u32(rb[0] + off, pk); stc_u32(rb[1] + off, pk);
            stc_u32(rb[2] + off, pk); stc_u32(rb[3] + off, pk);
        }
    }
    CSYNC();

    u32 ph = 0;   // mbarrier phase parity

    for (int t = 0; t < SEQL; t++) {
        const u32 cur = (u32)(t & 1);
        const u32 nxt = cur ^ 1u;

        // ===== fused MMA: gates2(t) [rows 0-127] and gates1(t+1) [rows 128-255]
        {
            const u32 ab = sb + OFF_HCAT + cur * HBUF + ld_off;
            float d2a[4] = {0,0,0,0}, d2b[4] = {0,0,0,0};
            float d1a[4] = {0,0,0,0}, d1b[4] = {0,0,0,0};
            #pragma unroll
            for (int kt = 0; kt < 8; kt++) {
                u32 r0v, r1v, r2v, r3v;
                ldmx4(r0v, r1v, r2v, r3v, ab + (u32)kt * 32u);
                mma16816(d2a, A2[kt], r0v, r1v);
                mma16816(d2b, A2[kt], r2v, r3v);
                mma16816(d1a, A1[kt], r0v, r1v);
                mma16816(d1b, A1[kt], r2v, r3v);
            }
            #pragma unroll
            for (int kt = 8; kt < 16; kt++) {
                u32 r0v, r1v, r2v, r3v;
                ldmx4(r0v, r1v, r2v, r3v, ab + (u32)kt * 32u);
                mma16816(d2a, A2[kt], r0v, r1v);
                mma16816(d2b, A2[kt], r2v, r3v);
            }
            int rr = w * 16 + fg;
            gst[(2 * ft)     * GROW + rr]     = d2a[0];
            gst[(2 * ft + 1) * GROW + rr]     = d2a[1];
            gst[(2 * ft)     * GROW + rr + 8] = d2a[2];
            gst[(2 * ft + 1) * GROW + rr + 8] = d2a[3];
            gst[(8 + 2 * ft)     * GROW + rr]     = d2b[0];
            gst[(9 + 2 * ft)     * GROW + rr]     = d2b[1];
            gst[(8 + 2 * ft)     * GROW + rr + 8] = d2b[2];
            gst[(9 + 2 * ft)     * GROW + rr + 8] = d2b[3];
            gst[(2 * ft)     * GROW + 128 + rr]     = d1a[0];
            gst[(2 * ft + 1) * GROW + 128 + rr]     = d1a[1];
            gst[(2 * ft)     * GROW + 128 + rr + 8] = d1a[2];
            gst[(2 * ft + 1) * GROW + 128 + rr + 8] = d1a[3];
            gst[(8 + 2 * ft)     * GROW + 128 + rr]     = d1b[0];
            gst[(9 + 2 * ft)     * GROW + 128 + rr]     = d1b[1];
            gst[(8 + 2 * ft)     * GROW + 128 + rr + 8] = d1b[2];
            gst[(9 + 2 * ft)     * GROW + 128 + rr + 8] = d1b[3];
        }
        __syncthreads();

        // ===== fused elementwise: layer2 -> h2(t), layer1 -> h1(t+1)
        if (L == 1 || t < SEQL - 1) {
            #pragma unroll
            for (int j = 0; j < 2; j++) {
                int b = bq + 8 * j;
                float xv = (L == 0) ? xsh[b * SEQL + t + 1] : 0.f;
                const float* gr = gst + b * GROW + grow_base + 2 * up;
                float2 vI = *(const float2*)(gr);
                float2 vF = *(const float2*)(gr + 32);
                float2 vG = *(const float2*)(gr + 64);
                float2 vO = *(const float2*)(gr + 96);
                float iA = siga(vI.x + fmaf(wiA[0], xv, bsA[0]));
                float fA = siga(vF.x + fmaf(wiA[1], xv, bsA[1]));
                float gA = tanha(vG.x + fmaf(wiA[2], xv, bsA[2]));
                float oA = siga(vO.x + fmaf(wiA[3], xv, bsA[3]));
                cA[j] = fmaf(fA, cA[j], iA * gA);
                float hA = oA * tanha(cA[j]);
                float iB = siga(vI.y + fmaf(wiB[0], xv, bsB[0]));
                float fB = siga(vF.y + fmaf(wiB[1], xv, bsB[1]));
                float gB = tanha(vG.y + fmaf(wiB[2], xv, bsB[2]));
                float oB = siga(vO.y + fmaf(wiB[3], xv, bsB[3]));
                cB[j] = fmaf(fB, cB[j], iB * gB);
                float hB = oB * tanha(cB[j]);
                u32 pk = f2h2(hA, hB);
                u32 off = nxt * HBUF + (u32)b * HROW + kbyte;
                stc_u32(rb[0] + off, pk); stc_u32(rb[1] + off, pk);
                stc_u32(rb[2] + off, pk); stc_u32(rb[3] + off, pk);
            }
        }

        // ===== cluster handshake: stores done -> arrive everywhere -> wait locally
        __syncthreads();
        if (tid == 0) {
            mbar_arrive_remote(rmb[0]); mbar_arrive_remote(rmb[1]);
            mbar_arrive_remote(rmb[2]); mbar_arrive_remote(rmb[3]);
        }
        mbar_wait(sb + OFF_MB, ph);
        ph ^= 1u;

        // ===== output: rank r writes batches 4r..4r+3 from its local full h2(t) replica
        if (w < 4) {
            int b = 4 * (int)rank + w;
            const char* hb = smem + OFF_HCAT + nxt * HBUF + (u32)b * HROW + 256u;
            uint2 hv = *(const uint2*)(hb + 8 * lane);
            __half2 h01 = *reinterpret_cast<__half2*>(&hv.x);
            __half2 h23 = *reinterpret_cast<__half2*>(&hv.y);
            float4 wl = *(const float4*)(wlin_s + 4 * lane);
            float p = wl.x * __low2float(h01) + wl.y * __high2float(h01)
                    + wl.z * __low2float(h23) + wl.w * __high2float(h23);
            #pragma unroll
            for (int o = 16; o; o >>= 1)
                p += __shfl_xor_sync(0xffffffffu, p, o);
            if (lane == 0) out[(b0 + b) * SEQL + t] = p + blin;
        }
    }
}

extern "C" void kernel_launch(void* const* d_in, const int* in_sizes, int n_in,
                              void* d_out, int out_size)
{
    static int init = 0;
    if (!init) {
        cudaFuncSetAttribute(lstm_fused_kernel, cudaFuncAttributeMaxDynamicSharedMemorySize, SMEM_TOTAL);
        init = 1;
    }
    lstm_fused_kernel<<<GRID, NT, SMEM_TOTAL>>>(
        (const float*)d_in[0], (const float*)d_in[1], (const float*)d_in[2],
        (const float*)d_in[3], (const float*)d_in[4], (const float*)d_in[5],
        (const float*)d_in[6], (const float*)d_in[7], (const float*)d_in[8],
        (const float*)d_in[9], (const float*)d_in[10], (float*)d_out);
}

// round 10
// speedup vs baseline: 1.0826x; 1.0826x over previous
#include <cuda_runtime.h>
#include <cuda_fp16.h>

typedef unsigned int u32;
typedef unsigned short u16;

#define SEQL 1000
#define CL   4
#define NT   512
#define GRID 128
#define NBC  16

// smem layout
#define HROW 528
#define HBUF (16 * HROW)                      // one hcat buffer (16 batches x 256k fp16 + pad)
#define GROW 260                              // gst row stride (f32 words)
#define OFF_HCAT 0u
#define OFF_GST  (2u * HBUF)                  // [16 batch][260] f32 ; cols 0-127 L2 gates, 128-255 L1 gates
#define OFF_X    (OFF_GST + 16u * GROW * 4u)  // [1000][16] f32, t-major
#define OFF_WLIN (OFF_X + 16u * SEQL * 4u)    // [128] f32
#define SMEM_TOTAL (OFF_WLIN + 512u + 16u)

static __device__ __forceinline__ u32 s2u(const void* p) {
    u32 a; asm("{ .reg .u64 t; cvta.to.shared.u64 t, %1; cvt.u32.u64 %0, t; }" : "=r"(a) : "l"(p));
    return a;
}
static __device__ __forceinline__ u32 mapa_rk(u32 addr, u32 rk) {
    u32 r; asm("mapa.shared::cluster.u32 %0, %1, %2;" : "=r"(r) : "r"(addr), "r"(rk));
    return r;
}
static __device__ __forceinline__ void stc_u16(u32 a, u16 v) {
    asm volatile("st.shared::cluster.u16 [%0], %1;" :: "r"(a), "h"(v) : "memory");
}
#define CSYNC() do { asm volatile("barrier.cluster.arrive.aligned;" ::: "memory"); \
                     asm volatile("barrier.cluster.wait.aligned;" ::: "memory"); } while (0)

static __device__ __forceinline__ void mma16816(float* d, const u32* a, u32 b0, u32 b1) {
    asm volatile("mma.sync.aligned.m16n8k16.row.col.f32.f16.f16.f32 "
        "{%0,%1,%2,%3}, {%4,%5,%6,%7}, {%8,%9}, {%0,%1,%2,%3};"
        : "+f"(d[0]), "+f"(d[1]), "+f"(d[2]), "+f"(d[3])
        : "r"(a[0]), "r"(a[1]), "r"(a[2]), "r"(a[3]), "r"(b0), "r"(b1));
}
static __device__ __forceinline__ void ldmx4(u32& r0, u32& r1, u32& r2, u32& r3, u32 addr) {
    asm volatile("ldmatrix.sync.aligned.m8n8.x4.shared.b16 {%0,%1,%2,%3}, [%4];"
        : "=r"(r0), "=r"(r1), "=r"(r2), "=r"(r3) : "r"(addr));
}
static __device__ __forceinline__ float tanha(float x) {
    float y; asm("tanh.approx.f32 %0, %1;" : "=f"(y) : "f"(x)); return y;
}
static __device__ __forceinline__ float siga(float x) {
    return fmaf(tanha(0.5f * x), 0.5f, 0.5f);
}
static __device__ __forceinline__ u32 f2h2(float lo, float hi) {
    __half2 h = __floats2half2_rn(lo, hi);
    return *reinterpret_cast<u32*>(&h);
}

__global__ __launch_bounds__(NT, 1) __cluster_dims__(CL, 1, 1)
void lstm_ws_kernel(const float* __restrict__ x,
                    const float* __restrict__ w_ih1,
                    const float* __restrict__ w_hh1,
                    const float* __restrict__ b_ih1,
                    const float* __restrict__ b_hh1,
                    const float* __restrict__ w_ih2,
                    const float* __restrict__ w_hh2,
                    const float* __restrict__ b_ih2,
                    const float* __restrict__ b_hh2,
                    const float* __restrict__ w_lin,
                    const float* __restrict__ b_lin,
                    float* __restrict__ out)
{
    extern __shared__ __align__(16) char smem[];
    const u32 sb = s2u(smem);
    const int tid  = threadIdx.x;
    const int lane = tid & 31;
    const int w    = tid >> 5;
    u32 rank; asm("mov.u32 %0, %%cluster_ctarank;" : "=r"(rank));
    const int b0 = (blockIdx.x >> 2) * NBC;

    const int fg = lane >> 2;
    const int ft = lane & 3;
    const bool isG2 = (w < 8);            // warps 0-7: layer2 MMA + layer2 ew

    // ---------- A fragments (fp16 weights, registers, loaded once)
    // G2: A[0..15] = [w_ih2|w_hh2] rows; G1: A[0..7] = w_hh1 rows
    const int wm = isG2 ? w : (w - 8);
    const int r0 = wm * 16 + fg;
    const int r1 = r0 + 8;
    const int G0 = (r0 >> 5) * 128 + (int)rank * 32 + (r0 & 31);
    const int G1r = (r1 >> 5) * 128 + (int)rank * 32 + (r1 & 31);

    u32 A[16][4];
    if (isG2) {
        #pragma unroll
        for (int kt = 0; kt < 16; kt++) {
            int k = kt * 16 + 2 * ft;
            const float* Wa = (k < 128)     ? (w_ih2 + k)     : (w_hh2 + k - 128);
            const float* Wb = (k + 8 < 128) ? (w_ih2 + k + 8) : (w_hh2 + k + 8 - 128);
            A[kt][0] = f2h2(Wa[G0 * 128],      Wa[G0 * 128 + 1]);
            A[kt][1] = f2h2(Wa[G1r * 128],     Wa[G1r * 128 + 1]);
            A[kt][2] = f2h2(Wb[G0 * 128],      Wb[G0 * 128 + 1]);
            A[kt][3] = f2h2(Wb[G1r * 128],     Wb[G1r * 128 + 1]);
        }
    } else {
        #pragma unroll
        for (int kt = 0; kt < 8; kt++) {
            int k = kt * 16 + 2 * ft;
            A[kt][0] = f2h2(w_hh1[G0 * 128 + k],      w_hh1[G0 * 128 + k + 1]);
            A[kt][1] = f2h2(w_hh1[G1r * 128 + k],     w_hh1[G1r * 128 + k + 1]);
            A[kt][2] = f2h2(w_hh1[G0 * 128 + k + 8],  w_hh1[G0 * 128 + k + 9]);
            A[kt][3] = f2h2(w_hh1[G1r * 128 + k + 8], w_hh1[G1r * 128 + k + 9]);
        }
    }

    // ---------- init smem
    for (u32 i = (u32)tid; i < 2u * HBUF / 4u; i += NT)
        ((u32*)smem)[i] = 0u;
    float* xsh = (float*)(smem + OFF_X);              // [t][16]
    for (int i = tid; i < NBC * SEQL; i += NT) {
        int b = i / SEQL, t = i % SEQL;
        xsh[t * 16 + b] = x[b0 * SEQL + i];
    }
    float* wlin_s = (float*)(smem + OFF_WLIN);
    if (tid < 128) wlin_s[tid] = w_lin[tid];

    // ---------- elementwise mapping: tid<256 -> layer2 ew; tid>=256 -> layer1 ew
    // each thread: 1 unit u (0..31), batches bq, bq+8
    const int idx = tid & 255;
    const int u   = idx >> 3;
    const int bq  = idx & 7;
    float wi[4], bs[4];
    #pragma unroll
    for (int g = 0; g < 4; g++) {
        int G = g * 128 + (int)rank * 32 + u;
        if (isG2) { wi[g] = 0.f;        bs[g] = b_ih2[G] + b_hh2[G]; }
        else      { wi[g] = w_ih1[G];   bs[g] = b_ih1[G] + b_hh1[G]; }
    }
    float c[2] = {0.f, 0.f};
    const float blin = b_lin[0];

    u32 rb[CL];
    #pragma unroll
    for (u32 rk = 0; rk < CL; rk++) rb[rk] = mapa_rk(sb + OFF_HCAT, rk);
    const u32 kbyte = (u32)((isG2 ? 128 : 0) + (int)rank * 32 + u) * 2u;

    float* gst = (float*)(smem + OFF_GST);
    const int grow_base = isG2 ? 0 : 128;   // ew read base; MMA stage base matches

    // ldmatrix per-lane base offset (proven R7/R8)
    const u32 ld_off = (u32)(((lane & 7) + ((lane >> 4) << 3)) * HROW + (((lane >> 3) & 1) << 4));

    __syncthreads();
    CSYNC();   // all CTAs zeroed buffers

    // ---------- prologue: h1(0) from x(0) (layer1 ew threads)
    if (!isG2) {
        #pragma unroll
        for (int j = 0; j < 2; j++) {
            int b = bq + 8 * j;
            float xv = xsh[b];            // t = 0
            float I = siga(fmaf(wi[0], xv, bs[0]));
            float G = tanha(fmaf(wi[2], xv, bs[2]));
            float O = siga(fmaf(wi[3], xv, bs[3]));
            c[j] = I * G;
            float hv = O * tanha(c[j]);
            u16 hh = __half_as_ushort(__float2half_rn(hv));
            u32 off = (u32)b * HROW + kbyte;   // buffer 0
            stc_u16(rb[0] + off, hh); stc_u16(rb[1] + off, hh);
            stc_u16(rb[2] + off, hh); stc_u16(rb[3] + off, hh);
        }
    }
    CSYNC();

    for (int t = 0; t < SEQL; t++) {
        const u32 cur = (u32)(t & 1);
        const u32 nxt = cur ^ 1u;

        // ===== MMA (warp-specialized)
        {
            const u32 ab = sb + OFF_HCAT + cur * HBUF + ld_off;
            const int rr = wm * 16 + fg;
            if (isG2) {
                // layer2 gates(t): K=256, two accumulator pairs (kt 0-7, 8-15)
                float da0[4] = {0,0,0,0}, db0[4] = {0,0,0,0};
                float da1[4] = {0,0,0,0}, db1[4] = {0,0,0,0};
                #pragma unroll
                for (int kt = 0; kt < 8; kt++) {
                    u32 r0v, r1v, r2v, r3v;
                    ldmx4(r0v, r1v, r2v, r3v, ab + (u32)kt * 32u);
                    mma16816(da0, A[kt], r0v, r1v);
                    mma16816(db0, A[kt], r2v, r3v);
                }
                #pragma unroll
                for (int kt = 8; kt < 16; kt++) {
                    u32 r0v, r1v, r2v, r3v;
                    ldmx4(r0v, r1v, r2v, r3v, ab + (u32)kt * 32u);
                    mma16816(da1, A[kt], r0v, r1v);
                    mma16816(db1, A[kt], r2v, r3v);
                }
                gst[(2 * ft)     * GROW + rr]     = da0[0] + da1[0];
                gst[(2 * ft + 1) * GROW + rr]     = da0[1] + da1[1];
                gst[(2 * ft)     * GROW + rr + 8] = da0[2] + da1[2];
                gst[(2 * ft + 1) * GROW + rr + 8] = da0[3] + da1[3];
                gst[(8 + 2 * ft) * GROW + rr]     = db0[0] + db1[0];
                gst[(9 + 2 * ft) * GROW + rr]     = db0[1] + db1[1];
                gst[(8 + 2 * ft) * GROW + rr + 8] = db0[2] + db1[2];
                gst[(9 + 2 * ft) * GROW + rr + 8] = db0[3] + db1[3];
            } else {
                // layer1 gates(t+1): K=128
                float da[4] = {0,0,0,0}, db[4] = {0,0,0,0};
                #pragma unroll
                for (int kt = 0; kt < 8; kt++) {
                    u32 r0v, r1v, r2v, r3v;
                    ldmx4(r0v, r1v, r2v, r3v, ab + (u32)kt * 32u);
                    mma16816(da, A[kt], r0v, r1v);
                    mma16816(db, A[kt], r2v, r3v);
                }
                gst[(2 * ft)     * GROW + 128 + rr]     = da[0];
                gst[(2 * ft + 1) * GROW + 128 + rr]     = da[1];
                gst[(2 * ft)     * GROW + 128 + rr + 8] = da[2];
                gst[(2 * ft + 1) * GROW + 128 + rr + 8] = da[3];
                gst[(8 + 2 * ft) * GROW + 128 + rr]     = db[0];
                gst[(9 + 2 * ft) * GROW + 128 + rr]     = db[1];
                gst[(8 + 2 * ft) * GROW + 128 + rr + 8] = db[2];
                gst[(9 + 2 * ft) * GROW + 128 + rr + 8] = db[3];
            }
        }
        __syncthreads();

        // ===== elementwise: tid<256 layer2 -> h2(t); tid>=256 layer1 -> h1(t+1)
        if (isG2 || t < SEQL - 1) {
            #pragma unroll
            for (int j = 0; j < 2; j++) {
                int b = bq + 8 * j;
                float xv = isG2 ? 0.f : xsh[(t + 1) * 16 + b];
                const float* gr = gst + b * GROW + grow_base + u;
                float I = siga(gr[0]   + fmaf(wi[0], xv, bs[0]));
                float F = siga(gr[32]  + fmaf(wi[1], xv, bs[1]));
                float G = tanha(gr[64] + fmaf(wi[2], xv, bs[2]));
                float O = siga(gr[96]  + fmaf(wi[3], xv, bs[3]));
                c[j] = fmaf(F, c[j], I * G);
                float hv = O * tanha(c[j]);
                u16 hh = __half_as_ushort(__float2half_rn(hv));
                u32 off = nxt * HBUF + (u32)b * HROW + kbyte;
                stc_u16(rb[0] + off, hh); stc_u16(rb[1] + off, hh);
                stc_u16(rb[2] + off, hh); stc_u16(rb[3] + off, hh);
            }
        }
        CSYNC();

        // ===== output: rank r writes batches 4r..4r+3 from local full h2(t) replica
        if (w < 4) {
            int b = 4 * (int)rank + w;
            const char* hb = smem + OFF_HCAT + nxt * HBUF + (u32)b * HROW + 256u;
            uint2 hv = *(const uint2*)(hb + 8 * lane);
            __half2 h01 = *reinterpret_cast<__half2*>(&hv.x);
            __half2 h23 = *reinterpret_cast<__half2*>(&hv.y);
            float4 wl = *(const float4*)(wlin_s + 4 * lane);
            float p = wl.x * __low2float(h01) + wl.y * __high2float(h01)
                    + wl.z * __low2float(h23) + wl.w * __high2float(h23);
            #pragma unroll
            for (int o = 16; o; o >>= 1)
                p += __shfl_xor_sync(0xffffffffu, p, o);
            if (lane == 0) out[(b0 + b) * SEQL + t] = p + blin;
        }
    }
}

extern "C" void kernel_launch(void* const* d_in, const int* in_sizes, int n_in,
                              void* d_out, int out_size)
{
    static int init = 0;
    if (!init) {
        cudaFuncSetAttribute(lstm_ws_kernel, cudaFuncAttributeMaxDynamicSharedMemorySize, SMEM_TOTAL);
        init = 1;
    }
    lstm_ws_kernel<<<GRID, NT, SMEM_TOTAL>>>(
        (const float*)d_in[0], (const float*)d_in[1], (const float*)d_in[2],
        (const float*)d_in[3], (const float*)d_in[4], (const float*)d_in[5],
        (const float*)d_in[6], (const float*)d_in[7], (const float*)d_in[8],
        (const float*)d_in[9], (const float*)d_in[10], (float*)d_out);
}

// round 11
// speedup vs baseline: 1.4416x; 1.3316x over previous
#include <cuda_runtime.h>
#include <cuda_fp16.h>

typedef unsigned int u32;
typedef unsigned short u16;

#define SEQL 1000
#define CL   4
#define NT   256
#define GRID 128
#define NBC  16

// smem layout
#define HROW 528
#define HBUF (16 * HROW)                      // one hcat buffer (16 batches x 256k fp16 + pad)
#define GROW 260                              // gst row stride (f32 words)
#define OFF_HCAT 0u
#define OFF_GST  (2u * HBUF)                  // [16 batch][260] f32 ; cols 0-127 L2 gates, 128-255 L1 gates
#define OFF_X    (OFF_GST + 16u * GROW * 4u)  // [1000][16] f32, t-major (conflict-free ew reads)
#define OFF_WLIN (OFF_X + 16u * SEQL * 4u)    // [128] f32
#define SMEM_TOTAL (OFF_WLIN + 512u + 16u)

static __device__ __forceinline__ u32 s2u(const void* p) {
    u32 a; asm("{ .reg .u64 t; cvta.to.shared.u64 t, %1; cvt.u32.u64 %0, t; }" : "=r"(a) : "l"(p));
    return a;
}
static __device__ __forceinline__ u32 mapa_rk(u32 addr, u32 rk) {
    u32 r; asm("mapa.shared::cluster.u32 %0, %1, %2;" : "=r"(r) : "r"(addr), "r"(rk));
    return r;
}
static __device__ __forceinline__ void stc_u32(u32 a, u32 v) {
    asm volatile("st.shared::cluster.u32 [%0], %1;" :: "r"(a), "r"(v) : "memory");
}
#define CSYNC() do { asm volatile("barrier.cluster.arrive.aligned;" ::: "memory"); \
                     asm volatile("barrier.cluster.wait.aligned;" ::: "memory"); } while (0)

static __device__ __forceinline__ void mma16816(float* d, const u32* a, u32 b0, u32 b1) {
    asm volatile("mma.sync.aligned.m16n8k16.row.col.f32.f16.f16.f32 "
        "{%0,%1,%2,%3}, {%4,%5,%6,%7}, {%8,%9}, {%0,%1,%2,%3};"
        : "+f"(d[0]), "+f"(d[1]), "+f"(d[2]), "+f"(d[3])
        : "r"(a[0]), "r"(a[1]), "r"(a[2]), "r"(a[3]), "r"(b0), "r"(b1));
}
static __device__ __forceinline__ void ldmx4(u32& r0, u32& r1, u32& r2, u32& r3, u32 addr) {
    asm volatile("ldmatrix.sync.aligned.m8n8.x4.shared.b16 {%0,%1,%2,%3}, [%4];"
        : "=r"(r0), "=r"(r1), "=r"(r2), "=r"(r3) : "r"(addr));
}
static __device__ __forceinline__ float tanha(float x) {
    float y; asm("tanh.approx.f32 %0, %1;" : "=f"(y) : "f"(x)); return y;
}
static __device__ __forceinline__ float siga(float x) {
    return fmaf(tanha(0.5f * x), 0.5f, 0.5f);
}
static __device__ __forceinline__ u32 f2h2(float lo, float hi) {
    __half2 h = __floats2half2_rn(lo, hi);
    return *reinterpret_cast<u32*>(&h);
}

__global__ __launch_bounds__(NT, 1) __cluster_dims__(CL, 1, 1)
void lstm_fused_kernel(const float* __restrict__ x,
                       const float* __restrict__ w_ih1,
                       const float* __restrict__ w_hh1,
                       const float* __restrict__ b_ih1,
                       const float* __restrict__ b_hh1,
                       const float* __restrict__ w_ih2,
                       const float* __restrict__ w_hh2,
                       const float* __restrict__ b_ih2,
                       const float* __restrict__ b_hh2,
                       const float* __restrict__ w_lin,
                       const float* __restrict__ b_lin,
                       float* __restrict__ out)
{
    extern __shared__ __align__(16) char smem[];
    const u32 sb = s2u(smem);
    const int tid  = threadIdx.x;
    const int lane = tid & 31;
    const int w    = tid >> 5;
    u32 rank; asm("mov.u32 %0, %%cluster_ctarank;" : "=r"(rank));
    const int b0 = (blockIdx.x >> 2) * NBC;

    const int fg = lane >> 2;
    const int ft = lane & 3;

    // ---------- A fragments (fp16 weights, registers, loaded once)
    const int r0 = w * 16 + fg;
    const int r1 = r0 + 8;
    const int G0 = (r0 >> 5) * 128 + (int)rank * 32 + (r0 & 31);
    const int G1 = (r1 >> 5) * 128 + (int)rank * 32 + (r1 & 31);

    u32 A1[8][4], A2[16][4];
    #pragma unroll
    for (int kt = 0; kt < 8; kt++) {
        int k = kt * 16 + 2 * ft;
        A1[kt][0] = f2h2(w_hh1[G0 * 128 + k],     w_hh1[G0 * 128 + k + 1]);
        A1[kt][1] = f2h2(w_hh1[G1 * 128 + k],     w_hh1[G1 * 128 + k + 1]);
        A1[kt][2] = f2h2(w_hh1[G0 * 128 + k + 8], w_hh1[G0 * 128 + k + 9]);
        A1[kt][3] = f2h2(w_hh1[G1 * 128 + k + 8], w_hh1[G1 * 128 + k + 9]);
    }
    #pragma unroll
    for (int kt = 0; kt < 16; kt++) {
        int k = kt * 16 + 2 * ft;
        const float* Wa = (k < 128)     ? (w_ih2 + k)     : (w_hh2 + k - 128);
        const float* Wb = (k + 8 < 128) ? (w_ih2 + k + 8) : (w_hh2 + k + 8 - 128);
        A2[kt][0] = f2h2(Wa[G0 * 128],     Wa[G0 * 128 + 1]);
        A2[kt][1] = f2h2(Wa[G1 * 128],     Wa[G1 * 128 + 1]);
        A2[kt][2] = f2h2(Wb[G0 * 128],     Wb[G0 * 128 + 1]);
        A2[kt][3] = f2h2(Wb[G1 * 128],     Wb[G1 * 128 + 1]);
    }

    // ---------- init smem
    for (u32 i = (u32)tid; i < 2u * HBUF / 4u; i += NT)
        ((u32*)smem)[i] = 0u;
    float* xsh = (float*)(smem + OFF_X);               // [t][16]
    for (int i = tid; i < NBC * SEQL; i += NT) {
        int b = i / SEQL, t = i % SEQL;
        xsh[t * 16 + b] = x[b0 * SEQL + i];
    }
    float* wlin_s = (float*)(smem + OFF_WLIN);
    if (tid < 128) wlin_s[tid] = w_lin[tid];

    // ---------- elementwise mapping: L (0=layer1, 1=layer2), unit pair up, batches bq, bq+8
    const int L  = tid >> 7;
    const int up = (tid >> 3) & 15;
    const int bq = tid & 7;
    float wiA[4], wiB[4], bsA[4], bsB[4];
    #pragma unroll
    for (int g = 0; g < 4; g++) {
        int GA = g * 128 + (int)rank * 32 + 2 * up;
        int GB = GA + 1;
        if (L == 0) {
            wiA[g] = w_ih1[GA];            wiB[g] = w_ih1[GB];
            bsA[g] = b_ih1[GA] + b_hh1[GA]; bsB[g] = b_ih1[GB] + b_hh1[GB];
        } else {
            wiA[g] = 0.f;                   wiB[g] = 0.f;
            bsA[g] = b_ih2[GA] + b_hh2[GA]; bsB[g] = b_ih2[GB] + b_hh2[GB];
        }
    }
    float cA[2] = {0.f, 0.f}, cB[2] = {0.f, 0.f};
    const float blin = b_lin[0];

    u32 rb[CL];
    #pragma unroll
    for (u32 rk = 0; rk < CL; rk++) rb[rk] = mapa_rk(sb + OFF_HCAT, rk);
    const u32 kbyte = (u32)((L ? 128 : 0) + (int)rank * 32 + 2 * up) * 2u;

    float* gst = (float*)(smem + OFF_GST);
    const int grow_base = L ? 0 : 128;    // gst read base for this thread's layer

    // ldmatrix per-lane base offset (proven R7/R8)
    const u32 ld_off = (u32)(((lane & 7) + ((lane >> 4) << 3)) * HROW + (((lane >> 3) & 1) << 4));

    __syncthreads();
    CSYNC();   // all CTAs zeroed their buffers

    // ---------- prologue: h1(0) from x(0) only (h1(-1)=0); write into buffer 0
    if (L == 0) {
        #pragma unroll
        for (int j = 0; j < 2; j++) {
            int b = bq + 8 * j;
            float xv = xsh[b];                          // t = 0
            float iA = siga(fmaf(wiA[0], xv, bsA[0]));
            float gA = tanha(fmaf(wiA[2], xv, bsA[2]));
            float oA = siga(fmaf(wiA[3], xv, bsA[3]));
            cA[j] = iA * gA;
            float hA = oA * tanha(cA[j]);
            float iB = siga(fmaf(wiB[0], xv, bsB[0]));
            float gB = tanha(fmaf(wiB[2], xv, bsB[2]));
            float oB = siga(fmaf(wiB[3], xv, bsB[3]));
            cB[j] = iB * gB;
            float hB = oB * tanha(cB[j]);
            u32 pk = f2h2(hA, hB);
            u32 off = (u32)b * HROW + kbyte;            // buffer 0
            stc_u32(rb[0] + off, pk); stc_u32(rb[1] + off, pk);
            stc_u32(rb[2] + off, pk); stc_u32(rb[3] + off, pk);
        }
    }
    CSYNC();

    for (int t = 0; t < SEQL; t++) {
        const u32 cur = (u32)(t & 1);
        const u32 nxt = cur ^ 1u;

        // ===== fused MMA: gates2(t) [cols 0-127] and gates1(t+1) [cols 128-255]
        // layer-2 K=256 split into two accumulator pairs -> max RAW chain 8 HMMA
        {
            const u32 ab = sb + OFF_HCAT + cur * HBUF + ld_off;
            float d2a0[4] = {0,0,0,0}, d2b0[4] = {0,0,0,0};
            float d2a1[4] = {0,0,0,0}, d2b1[4] = {0,0,0,0};
            float d1a[4]  = {0,0,0,0}, d1b[4]  = {0,0,0,0};
            #pragma unroll
            for (int kt = 0; kt < 8; kt++) {
                u32 r0v, r1v, r2v, r3v;
                ldmx4(r0v, r1v, r2v, r3v, ab + (u32)kt * 32u);
                mma16816(d2a0, A2[kt], r0v, r1v);
                mma16816(d2b0, A2[kt], r2v, r3v);
                mma16816(d1a,  A1[kt], r0v, r1v);
                mma16816(d1b,  A1[kt], r2v, r3v);
            }
            #pragma unroll
            for (int kt = 8; kt < 16; kt++) {
                u32 r0v, r1v, r2v, r3v;
                ldmx4(r0v, r1v, r2v, r3v, ab + (u32)kt * 32u);
                mma16816(d2a1, A2[kt], r0v, r1v);
                mma16816(d2b1, A2[kt], r2v, r3v);
            }
            int rr = w * 16 + fg;
            gst[(2 * ft)     * GROW + rr]     = d2a0[0] + d2a1[0];
            gst[(2 * ft + 1) * GROW + rr]     = d2a0[1] + d2a1[1];
            gst[(2 * ft)     * GROW + rr + 8] = d2a0[2] + d2a1[2];
            gst[(2 * ft + 1) * GROW + rr + 8] = d2a0[3] + d2a1[3];
            gst[(8 + 2 * ft) * GROW + rr]     = d2b0[0] + d2b1[0];
            gst[(9 + 2 * ft) * GROW + rr]     = d2b0[1] + d2b1[1];
            gst[(8 + 2 * ft) * GROW + rr + 8] = d2b0[2] + d2b1[2];
            gst[(9 + 2 * ft) * GROW + rr + 8] = d2b0[3] + d2b1[3];
            gst[(2 * ft)     * GROW + 128 + rr]     = d1a[0];
            gst[(2 * ft + 1) * GROW + 128 + rr]     = d1a[1];
            gst[(2 * ft)     * GROW + 128 + rr + 8] = d1a[2];
            gst[(2 * ft + 1) * GROW + 128 + rr + 8] = d1a[3];
            gst[(8 + 2 * ft) * GROW + 128 + rr]     = d1b[0];
            gst[(9 + 2 * ft) * GROW + 128 + rr]     = d1b[1];
            gst[(8 + 2 * ft) * GROW + 128 + rr + 8] = d1b[2];
            gst[(9 + 2 * ft) * GROW + 128 + rr + 8] = d1b[3];
        }
        __syncthreads();

        // ===== fused elementwise: layer2 -> h2(t), layer1 -> h1(t+1)
        if (L == 1 || t < SEQL - 1) {
            #pragma unroll
            for (int j = 0; j < 2; j++) {
                int b = bq + 8 * j;
                float xv = (L == 0) ? xsh[(t + 1) * 16 + b] : 0.f;
                const float* gr = gst + b * GROW + grow_base + 2 * up;
                float2 vI = *(const float2*)(gr);
                float2 vF = *(const float2*)(gr + 32);
                float2 vG = *(const float2*)(gr + 64);
                float2 vO = *(const float2*)(gr + 96);
                float iA = siga(vI.x + fmaf(wiA[0], xv, bsA[0]));
                float fA = siga(vF.x + fmaf(wiA[1], xv, bsA[1]));
                float gA = tanha(vG.x + fmaf(wiA[2], xv, bsA[2]));
                float oA = siga(vO.x + fmaf(wiA[3], xv, bsA[3]));
                cA[j] = fmaf(fA, cA[j], iA * gA);
                float hA = oA * tanha(cA[j]);
                float iB = siga(vI.y + fmaf(wiB[0], xv, bsB[0]));
                float fB = siga(vF.y + fmaf(wiB[1], xv, bsB[1]));
                float gB = tanha(vG.y + fmaf(wiB[2], xv, bsB[2]));
                float oB = siga(vO.y + fmaf(wiB[3], xv, bsB[3]));
                cB[j] = fmaf(fB, cB[j], iB * gB);
                float hB = oB * tanha(cB[j]);
                u32 pk = f2h2(hA, hB);
                u32 off = nxt * HBUF + (u32)b * HROW + kbyte;
                stc_u32(rb[0] + off, pk); stc_u32(rb[1] + off, pk);
                stc_u32(rb[2] + off, pk); stc_u32(rb[3] + off, pk);
            }
        }
        CSYNC();

        // ===== output: rank r writes batches 4r..4r+3 from its local full h2(t) replica
        if (w < 4) {
            int b = 4 * (int)rank + w;
            const char* hb = smem + OFF_HCAT + nxt * HBUF + (u32)b * HROW + 256u;
            uint2 hv = *(const uint2*)(hb + 8 * lane);
            __half2 h01 = *reinterpret_cast<__half2*>(&hv.x);
            __half2 h23 = *reinterpret_cast<__half2*>(&hv.y);
            float4 wl = *(const float4*)(wlin_s + 4 * lane);
            float p = wl.x * __low2float(h01) + wl.y * __high2float(h01)
                    + wl.z * __low2float(h23) + wl.w * __high2float(h23);
            #pragma unroll
            for (int o = 16; o; o >>= 1)
                p += __shfl_xor_sync(0xffffffffu, p, o);
            if (lane == 0) out[(b0 + b) * SEQL + t] = p + blin;
        }
    }
}

extern "C" void kernel_launch(void* const* d_in, const int* in_sizes, int n_in,
                              void* d_out, int out_size)
{
    static int init = 0;
    if (!init) {
        cudaFuncSetAttribute(lstm_fused_kernel, cudaFuncAttributeMaxDynamicSharedMemorySize, SMEM_TOTAL);
        init = 1;
    }
    lstm_fused_kernel<<<GRID, NT, SMEM_TOTAL>>>(
        (const float*)d_in[0], (const float*)d_in[1], (const float*)d_in[2],
        (const float*)d_in[3], (const float*)d_in[4], (const float*)d_in[5],
        (const float*)d_in[6], (const float*)d_in[7], (const float*)d_in[8],
        (const float*)d_in[9], (const float*)d_in[10], (float*)d_out);
}